// round 10
// baseline (speedup 1.0000x reference)
#include <cuda_runtime.h>
#include <cuda_bf16.h>
#include <cstdint>

// ---------------- problem constants ----------------
#define CLASSES   100000
#define KDIM      512
#define BATCHN    512
#define NCTA      782                  // class tiles of 128
#define PPAD      784                  // padded partial stride per batch row
#define NCHUNK    8                    // K chunks of 64
#define EXPK      92.33248261689366f   // 64 * log2(e)

static constexpr float C_COS_M = 0.8775825618903728f;   // cos(0.5)
static constexpr float C_SIN_M = 0.479425538604203f;    // sin(0.5)
static constexpr float C_TH    = -0.8775825618903728f;  // cos(pi-0.5)
static constexpr float C_MM    = 0.23971276930210156f;  // sin(pi-0.5)*0.5

// ---------------- device scratch (static: no allocations allowed) ----------------
__device__ __nv_bfloat16 g_xn[BATCHN * KDIM];          // normalized x, bf16
__device__ float g_partials[(size_t)BATCHN * PPAD];    // per (b, class-tile) exp sums
__device__ float g_cost[BATCHN];                       // cosine at target class
__device__ float g_lossb[BATCHN];                      // per-sample loss
__device__ int   g_tgt[BATCHN];                        // targets as int32 (dtype-robust)

// ---------------- helpers ----------------
__device__ __forceinline__ uint32_t smem_u32(const void* p) {
    uint32_t a;
    asm("{ .reg .u64 t; cvta.to.shared.u64 t, %1; cvt.u32.u64 %0, t; }" : "=r"(a) : "l"(p));
    return a;
}
__device__ __forceinline__ void cp_async16_cg(uint32_t saddr, const void* gptr) {
    asm volatile("cp.async.cg.shared.global [%0], [%1], 16;"
                 :: "r"(saddr), "l"(__cvta_generic_to_global(gptr)));
}
__device__ __forceinline__ void cp_async16_ca(uint32_t saddr, const void* gptr) {
    asm volatile("cp.async.ca.shared.global [%0], [%1], 16;"
                 :: "r"(saddr), "l"(__cvta_generic_to_global(gptr)));
}
__device__ __forceinline__ void cp_commit() {
    asm volatile("cp.async.commit_group;" ::: "memory");
}
template <int N>
__device__ __forceinline__ void cp_wait() {
    asm volatile("cp.async.wait_group %0;" :: "n"(N) : "memory");
}
__device__ __forceinline__ void ldsm_x4(uint32_t* r, uint32_t addr) {
    asm volatile("ldmatrix.sync.aligned.m8n8.x4.shared.b16 {%0,%1,%2,%3}, [%4];"
                 : "=r"(r[0]), "=r"(r[1]), "=r"(r[2]), "=r"(r[3]) : "r"(addr));
}
__device__ __forceinline__ void mma_bf16(float* d, const uint32_t* a, uint32_t b0, uint32_t b1) {
    asm volatile(
        "mma.sync.aligned.m16n8k16.row.col.f32.bf16.bf16.f32 "
        "{%0,%1,%2,%3}, {%4,%5,%6,%7}, {%8,%9}, {%0,%1,%2,%3};"
        : "+f"(d[0]), "+f"(d[1]), "+f"(d[2]), "+f"(d[3])
        : "r"(a[0]), "r"(a[1]), "r"(a[2]), "r"(a[3]), "r"(b0), "r"(b1));
}
__device__ __forceinline__ uint32_t swz(uint32_t off) {  // XOR swizzle on 128B rows
    return off ^ ((off >> 3) & 0x70);
}
__device__ __forceinline__ uint32_t pack_bf16x2(float a, float b) {
    __nv_bfloat162 p = __floats2bfloat162_rn(a, b);
    return *(uint32_t*)&p;
}

// ---------------- dynamic smem layout for fused GEMM ----------------
#define OFF_A     0          // A bf16, 3 stages * 16384
#define OFF_BH    49152      // B bf16 tile (single), 16384
#define OFF_BF32  65536      // B f32 staging: 128 rows * 304B = 38912
#define BSTRIDE   304        // 19*16 -> conflict-free 8-phase LDS
#define OFF_SSA   104448     // 128 f32
#define OFF_SSB   104960     // 128 f32
#define OFF_RSUM  105472     // 128*2 f32 = 1024
#define SMEM_DYN  (106496 + 1024)

// ======================= K-1: dtype-robust target conversion =======================
__global__ void __launch_bounds__(512) k_prep_targets(const int* __restrict__ t32) {
    __shared__ int nz;
    int tid = threadIdx.x;
    if (tid == 0) nz = 0;
    __syncthreads();
    int v = t32[tid];                       // first 512 int32 words (2048 bytes, safe)
    if ((tid & 1) && v != 0) atomicAdd(&nz, 1);
    __syncthreads();
    bool is64 = (nz == 0);
    g_tgt[tid] = is64 ? t32[2 * tid] : v;
}

// ======================= K1: normalize x -> bf16 =======================
__global__ void __launch_bounds__(128) k_norm_x(const float* __restrict__ x) {
    __shared__ float red[4];
    int b = blockIdx.x;
    int tid = threadIdx.x;
    float4 v = *(const float4*)(x + (size_t)b * KDIM + tid * 4);
    float sq = v.x * v.x + v.y * v.y + v.z * v.z + v.w * v.w;
    #pragma unroll
    for (int m = 16; m >= 1; m >>= 1) sq += __shfl_xor_sync(0xffffffffu, sq, m);
    if ((tid & 31) == 0) red[tid >> 5] = sq;
    __syncthreads();
    float inv = 1.0f / fmaxf(sqrtf(red[0] + red[1] + red[2] + red[3]), 1e-12f);
    uint2 pk;
    pk.x = pack_bf16x2(v.x * inv, v.y * inv);
    pk.y = pack_bf16x2(v.z * inv, v.w * inv);
    *(uint2*)(&g_xn[(size_t)b * KDIM + tid * 4]) = pk;
}

// ======================= K2: fused HMMA GEMM (in-kernel w-normalize) + partial LSE ====
// 256 threads, 8 warps 4x2, warp tile 32x64, CTA tile 128 batch x 128 class.
// B read as raw f32 (cp.async staged), converted to bf16 + row sumsq on chip.
__global__ void __launch_bounds__(256, 2) k_gemm(const float* __restrict__ w) {
    extern __shared__ char dsm[];
    uint32_t base = smem_u32(dsm);
    uint32_t SB = (base + 1023u) & ~1023u;
    char* SA = dsm + (SB - base);

    int tid = threadIdx.x;
    int wid = tid >> 5;
    int lid = tid & 31;
    int warpM = wid >> 1;          // 0..3  (32 batch rows each)
    int warpN = wid & 1;           // 0..1  (64 class cols each)

    int ctile = blockIdx.x >> 2;
    int btile = blockIdx.x & 3;
    int cls0 = ctile * 128;
    int b0 = btile * 128;

    // ---- A loader (bf16 from g_xn, 3 stages) ----
    int lrow = tid >> 3;                   // 0..31
    int lcol = (tid & 7) * 16;
    uint32_t stA_sw = SB + OFF_A + (uint32_t)(lrow * 128 + (lcol ^ ((lrow & 7) << 4)));
    const char* pA = (const char*)g_xn + (size_t)b0 * 1024 + lrow * 1024 + (tid & 7) * 16;
    auto ld_A = [&](int kc, int st) {
        #pragma unroll
        for (int i = 0; i < 4; i++)
            cp_async16_ca(stA_sw + st * 16384 + i * 4096, pA + i * 32768 + kc * 128);
    };

    // ---- B f32 loader: thread -> (row r, half h) ----
    int br = tid & 127;                    // class row in tile
    int bh = tid >> 7;                     // half of the 64-f32 chunk row
    bool okrow = (cls0 + br) < CLASSES;
    uint32_t sB32 = SB + OFF_BF32 + (uint32_t)(br * BSTRIDE + bh * 128);
    const char* pW = (const char*)w + (size_t)(cls0 + br) * 2048 + bh * 128;
    auto ld_B = [&](int kc) {
        if (okrow) {
            #pragma unroll
            for (int i = 0; i < 8; i++)
                cp_async16_cg(sB32 + i * 16, pW + kc * 256 + i * 16);
        }
    };

    float* ssa = (float*)(SA + OFF_SSA);
    float* ssb = (float*)(SA + OFF_SSB);
    float* myss = bh ? (ssb + br) : (ssa + br);

    // ---- LDSM bases ----
    int lr = lid & 15;
    int lh = (lid >> 4) * 16;
    uint32_t pat = (uint32_t)((lr & 7) << 4);
    uint32_t ko[4];
    #pragma unroll
    for (int ks = 0; ks < 4; ks++) ko[ks] = (uint32_t)((ks * 32 + lh) ^ pat);
    uint32_t ldA = SB + OFF_A + (uint32_t)((warpM * 32 + lr) * 128);
    uint32_t ldB = SB + OFF_BH + (uint32_t)((warpN * 64 + lr) * 128);

    float acc[2][8][4];
    #pragma unroll
    for (int i = 0; i < 2; i++)
        #pragma unroll
        for (int j = 0; j < 8; j++)
            #pragma unroll
            for (int q = 0; q < 4; q++) acc[i][j][q] = 0.0f;

    // ---- prologue ----
    if (tid < 128) { ssa[tid] = 0.0f; ssb[tid] = 0.0f; }
    if (!okrow) {                       // zero padded rows once; never overwritten
        float4 z = make_float4(0.f, 0.f, 0.f, 0.f);
        #pragma unroll
        for (int i = 0; i < 8; i++)
            *(float4*)(SA + OFF_BF32 + br * BSTRIDE + bh * 128 + i * 16) = z;
    }
    ld_A(0, 0);
    ld_B(0);
    cp_commit();
    ld_A(1, 1);
    cp_commit();
    cp_wait<1>();         // {A0,B0} complete
    __syncthreads();

    uint32_t bfr[2][4][4];
    uint32_t afr[2][2][4];

    #pragma unroll
    for (int kc = 0; kc < NCHUNK; kc++) {
        // step1: read f32 stage + row sumsq
        float4 v[8];
        const float4* pf = (const float4*)(SA + OFF_BF32 + br * BSTRIDE + bh * 128);
        #pragma unroll
        for (int i = 0; i < 8; i++) v[i] = pf[i];
        float s = 0.0f;
        #pragma unroll
        for (int i = 0; i < 8; i++)
            s += v[i].x * v[i].x + v[i].y * v[i].y + v[i].z * v[i].z + v[i].w * v[i].w;
        *myss += s;
        __syncthreads();                          // f32 stage free for reuse

        // step3: prefetch next B f32 + A(kc+2)
        if (kc + 1 < NCHUNK) {
            ld_B(kc + 1);
            if (kc + 2 < NCHUNK) ld_A(kc + 2, (kc + 2) % 3);
            cp_commit();
        }

        // step4: convert -> bf16 tile (swizzled)
        #pragma unroll
        for (int j = 0; j < 4; j++) {
            uint4 u;
            u.x = pack_bf16x2(v[2 * j].x, v[2 * j].y);
            u.y = pack_bf16x2(v[2 * j].z, v[2 * j].w);
            u.z = pack_bf16x2(v[2 * j + 1].x, v[2 * j + 1].y);
            u.w = pack_bf16x2(v[2 * j + 1].z, v[2 * j + 1].w);
            *(uint4*)(SA + OFF_BH + swz((uint32_t)(br * 128 + bh * 64 + j * 16))) = u;
        }
        __syncthreads();                          // bf16 tile visible

        // step6: LDSM + MMA
        const uint32_t sOffA = (uint32_t)((kc % 3) * 16384);
        #pragma unroll
        for (int nt4 = 0; nt4 < 4; nt4++)
            ldsm_x4(bfr[0][nt4], ldB + nt4 * 2048 + ko[0]);
        #pragma unroll
        for (int mt = 0; mt < 2; mt++)
            ldsm_x4(afr[0][mt], ldA + sOffA + mt * 2048 + ko[0]);

        #pragma unroll
        for (int ks = 0; ks < 4; ks++) {
            int cur = ks & 1;
            int nxt = cur ^ 1;
            if (ks < 3) {
                #pragma unroll
                for (int nt4 = 0; nt4 < 4; nt4++)
                    ldsm_x4(bfr[nxt][nt4], ldB + nt4 * 2048 + ko[ks + 1]);
                #pragma unroll
                for (int mt = 0; mt < 2; mt++)
                    ldsm_x4(afr[nxt][mt], ldA + sOffA + mt * 2048 + ko[ks + 1]);
            }
            #pragma unroll
            for (int mt = 0; mt < 2; mt++) {
                #pragma unroll
                for (int nt4 = 0; nt4 < 4; nt4++) {
                    mma_bf16(acc[mt][nt4 * 2 + 0], afr[cur][mt], bfr[cur][nt4][0], bfr[cur][nt4][2]);
                    mma_bf16(acc[mt][nt4 * 2 + 1], afr[cur][mt], bfr[cur][nt4][1], bfr[cur][nt4][3]);
                }
            }
        }

        if (kc < NCHUNK - 1) {
            cp_wait<0>();        // B(kc+1) + A(kc+1/kc+2) complete
            __syncthreads();     // visible to all; buffers safe to cycle
        }
    }

    // ---------------- epilogue: norms + deterministic partial LSE ----------------
    __syncthreads();
    if (tid < 128) {
        float sc = ssa[tid] + ssb[tid];
        ssa[tid] = 1.0f / fmaxf(sqrtf(sc), 1e-12f);
    }
    __syncthreads();

    int g = lid >> 2;
    int tg = lid & 3;
    float invc[16];
    #pragma unroll
    for (int nt = 0; nt < 8; nt++) {
        invc[nt * 2 + 0] = ssa[warpN * 64 + nt * 8 + tg * 2 + 0];
        invc[nt * 2 + 1] = ssa[warpN * 64 + nt * 8 + tg * 2 + 1];
    }

    float* rsum = (float*)(SA + OFF_RSUM);
    float rs[4] = {0.f, 0.f, 0.f, 0.f};
    #pragma unroll
    for (int mt = 0; mt < 2; mt++) {
        int rlo = warpM * 32 + mt * 16 + g;
        int rhi = rlo + 8;
        int tlo = g_tgt[b0 + rlo];
        int thi = g_tgt[b0 + rhi];
        #pragma unroll
        for (int nt = 0; nt < 8; nt++) {
            int colb = warpN * 64 + nt * 8 + tg * 2;
            #pragma unroll
            for (int q = 0; q < 4; q++) {
                int cls = cls0 + colb + (q & 1);
                float cosv = acc[mt][nt][q] * invc[nt * 2 + (q & 1)];
                int row = (q < 2) ? rlo : rhi;
                int t = (q < 2) ? tlo : thi;
                if (cls == t) {
                    g_cost[b0 + row] = cosv;
                } else if (cls < CLASSES) {
                    rs[mt * 2 + (q >> 1)] += exp2f(fmaf(EXPK, cosv, -EXPK));
                }
            }
        }
    }
    #pragma unroll
    for (int i = 0; i < 4; i++) {
        rs[i] += __shfl_xor_sync(0xffffffffu, rs[i], 1);
        rs[i] += __shfl_xor_sync(0xffffffffu, rs[i], 2);
    }
    if (tg == 0) {
        #pragma unroll
        for (int mt = 0; mt < 2; mt++) {
            int rlo = warpM * 32 + mt * 16 + g;
            rsum[rlo * 2 + warpN] = rs[mt * 2 + 0];
            rsum[(rlo + 8) * 2 + warpN] = rs[mt * 2 + 1];
        }
    }
    __syncthreads();
    if (tid < 128) {
        g_partials[(size_t)(b0 + tid) * PPAD + ctile] = rsum[tid * 2] + rsum[tid * 2 + 1];
    }
}

// ======================= K3: per-batch reduce + margin math =======================
__global__ void __launch_bounds__(128) k_reduce_b() {
    __shared__ float red[4];
    int b = blockIdx.x;
    int tid = threadIdx.x;
    float acc = 0.0f;
    for (int i = tid; i < NCTA; i += 128) acc += g_partials[(size_t)b * PPAD + i];
    #pragma unroll
    for (int m = 16; m >= 1; m >>= 1) acc += __shfl_xor_sync(0xffffffffu, acc, m);
    if ((tid & 31) == 0) red[tid >> 5] = acc;
    __syncthreads();
    if (tid == 0) {
        float S = red[0] + red[1] + red[2] + red[3];
        float ct = g_cost[b];
        float st = sqrtf(fmaxf(1.0f - ct * ct, 0.0f));
        float phi = ct * C_COS_M - st * C_SIN_M;
        phi = (ct > C_TH) ? phi : (ct - C_MM);
        S += exp2f(EXPK * (phi - 1.0f));
        g_lossb[b] = 64.0f + logf(S) - 64.0f * phi;
    }
}

// ======================= K4: mean over batch =======================
__global__ void __launch_bounds__(512) k_finalize(float* __restrict__ out) {
    __shared__ float red[16];
    int tid = threadIdx.x;
    float v = g_lossb[tid];
    #pragma unroll
    for (int m = 16; m >= 1; m >>= 1) v += __shfl_xor_sync(0xffffffffu, v, m);
    if ((tid & 31) == 0) red[tid >> 5] = v;
    __syncthreads();
    if (tid < 16) {
        float s = red[tid];
        #pragma unroll
        for (int m = 8; m >= 1; m >>= 1) s += __shfl_xor_sync(0xffffu, s, m);
        if (tid == 0) out[0] = s * (1.0f / (float)BATCHN);
    }
}

// ======================= launch =======================
extern "C" void kernel_launch(void* const* d_in, const int* in_sizes, int n_in,
                              void* d_out, int out_size) {
    const float* x = (const float*)d_in[0];
    const float* w = (const float*)d_in[1];
    const int* tgt_raw = (const int*)d_in[2];
    float* out = (float*)d_out;

    cudaFuncSetAttribute(k_gemm, cudaFuncAttributeMaxDynamicSharedMemorySize, SMEM_DYN);

    k_prep_targets<<<1, 512>>>(tgt_raw);
    k_norm_x<<<BATCHN, 128>>>(x);
    k_gemm<<<NCTA * 4, 256, SMEM_DYN>>>(w);
    k_reduce_b<<<BATCHN, 128>>>();
    k_finalize<<<1, 512>>>(out);
}

// round 11
// speedup vs baseline: 1.7761x; 1.7761x over previous
#include <cuda_runtime.h>
#include <cuda_bf16.h>
#include <cstdint>

// ---------------- problem constants ----------------
#define CLASSES   100000
#define CPAD      100096               // 782*128 padded classes
#define KDIM      512
#define BATCHN    512
#define NCTA      782                  // class tiles of 128
#define PPAD      784                  // padded partial stride per batch row
#define NCHUNK    8                    // K chunks of 64
#define EXPK      92.33248261689366f   // 64 * log2(e)

static constexpr float C_COS_M = 0.8775825618903728f;   // cos(0.5)
static constexpr float C_SIN_M = 0.479425538604203f;    // sin(0.5)
static constexpr float C_TH    = -0.8775825618903728f;  // cos(pi-0.5)
static constexpr float C_MM    = 0.23971276930210156f;  // sin(pi-0.5)*0.5

// ---------------- device scratch (static: no allocations allowed) ----------------
__device__ __nv_bfloat16 g_xn[BATCHN * KDIM];          // normalized x, bf16
__device__ __nv_bfloat16 g_wb[(size_t)CPAD * KDIM];    // normalized w, bf16 (zero-padded)
__device__ float g_partials[(size_t)BATCHN * PPAD];    // per (b, class-tile) exp sums
__device__ float g_cost[BATCHN];                       // cosine at target class
__device__ float g_lossb[BATCHN];                      // per-sample loss
__device__ int   g_tgt[BATCHN];                        // targets as int32 (dtype-robust)

// ---------------- helpers ----------------
__device__ __forceinline__ uint32_t smem_u32(const void* p) {
    uint32_t a;
    asm("{ .reg .u64 t; cvta.to.shared.u64 t, %1; cvt.u32.u64 %0, t; }" : "=r"(a) : "l"(p));
    return a;
}
__device__ __forceinline__ void cp_async16_cg(uint32_t saddr, const void* gptr) {
    asm volatile("cp.async.cg.shared.global [%0], [%1], 16;"
                 :: "r"(saddr), "l"(__cvta_generic_to_global(gptr)));
}
__device__ __forceinline__ void cp_async16_ca(uint32_t saddr, const void* gptr) {
    asm volatile("cp.async.ca.shared.global [%0], [%1], 16;"
                 :: "r"(saddr), "l"(__cvta_generic_to_global(gptr)));
}
__device__ __forceinline__ void cp_commit() {
    asm volatile("cp.async.commit_group;" ::: "memory");
}
template <int N>
__device__ __forceinline__ void cp_wait() {
    asm volatile("cp.async.wait_group %0;" :: "n"(N) : "memory");
}
__device__ __forceinline__ void ldsm_x4(uint32_t* r, uint32_t addr) {
    asm volatile("ldmatrix.sync.aligned.m8n8.x4.shared.b16 {%0,%1,%2,%3}, [%4];"
                 : "=r"(r[0]), "=r"(r[1]), "=r"(r[2]), "=r"(r[3]) : "r"(addr));
}
__device__ __forceinline__ void mma_bf16(float* d, const uint32_t* a, uint32_t b0, uint32_t b1) {
    asm volatile(
        "mma.sync.aligned.m16n8k16.row.col.f32.bf16.bf16.f32 "
        "{%0,%1,%2,%3}, {%4,%5,%6,%7}, {%8,%9}, {%0,%1,%2,%3};"
        : "+f"(d[0]), "+f"(d[1]), "+f"(d[2]), "+f"(d[3])
        : "r"(a[0]), "r"(a[1]), "r"(a[2]), "r"(a[3]), "r"(b0), "r"(b1));
}
__device__ __forceinline__ uint32_t pack_bf16x2(float a, float b) {
    __nv_bfloat162 p = __floats2bfloat162_rn(a, b);
    return *(uint32_t*)&p;
}

// ---------------- dynamic smem layout for GEMM (3-stage) ----------------
#define SM_STAGE  32768
#define SM_RSUM   98304     // 128*2 f32 = 1024
#define SM_TGT    99328     // 128 int = 512
#define SMEM_DYN  (99840 + 1024)

// ======================= K-1: dtype-robust target conversion =======================
__global__ void __launch_bounds__(512) k_prep_targets(const int* __restrict__ t32) {
    __shared__ int nz;
    int tid = threadIdx.x;
    if (tid == 0) nz = 0;
    __syncthreads();
    int v = t32[tid];                       // first 512 int32 words (2048 bytes, safe)
    if ((tid & 1) && v != 0) atomicAdd(&nz, 1);
    __syncthreads();
    bool is64 = (nz == 0);
    g_tgt[tid] = is64 ? t32[2 * tid] : v;
}

// ======================= K0: normalize weights -> bf16 (warp per row) =======================
__global__ void __launch_bounds__(128) k_norm_w(const float* __restrict__ w) {
    int row = blockIdx.x * 4 + (threadIdx.x >> 5);   // one warp per row
    int lane = threadIdx.x & 31;
    if (row >= CLASSES) {
        #pragma unroll
        for (int i = 0; i < 4; i++)
            *(uint2*)(&g_wb[(size_t)row * KDIM + i * 128 + lane * 4]) = make_uint2(0u, 0u);
        return;
    }
    float4 v[4];
    float sq = 0.0f;
    #pragma unroll
    for (int i = 0; i < 4; i++) {
        v[i] = *(const float4*)(w + (size_t)row * KDIM + i * 128 + lane * 4);
        sq += v[i].x * v[i].x + v[i].y * v[i].y + v[i].z * v[i].z + v[i].w * v[i].w;
    }
    #pragma unroll
    for (int m = 16; m >= 1; m >>= 1) sq += __shfl_xor_sync(0xffffffffu, sq, m);
    float inv = 1.0f / fmaxf(sqrtf(sq), 1e-12f);
    #pragma unroll
    for (int i = 0; i < 4; i++) {
        uint2 pk;
        pk.x = pack_bf16x2(v[i].x * inv, v[i].y * inv);
        pk.y = pack_bf16x2(v[i].z * inv, v[i].w * inv);
        *(uint2*)(&g_wb[(size_t)row * KDIM + i * 128 + lane * 4]) = pk;
    }
}

// ======================= K1: normalize x -> bf16 =======================
__global__ void __launch_bounds__(128) k_norm_x(const float* __restrict__ x) {
    __shared__ float red[4];
    int b = blockIdx.x;
    int tid = threadIdx.x;
    float4 v = *(const float4*)(x + (size_t)b * KDIM + tid * 4);
    float sq = v.x * v.x + v.y * v.y + v.z * v.z + v.w * v.w;
    #pragma unroll
    for (int m = 16; m >= 1; m >>= 1) sq += __shfl_xor_sync(0xffffffffu, sq, m);
    if ((tid & 31) == 0) red[tid >> 5] = sq;
    __syncthreads();
    float inv = 1.0f / fmaxf(sqrtf(red[0] + red[1] + red[2] + red[3]), 1e-12f);
    uint2 pk;
    pk.x = pack_bf16x2(v.x * inv, v.y * inv);
    pk.y = pack_bf16x2(v.z * inv, v.w * inv);
    *(uint2*)(&g_xn[(size_t)b * KDIM + tid * 4]) = pk;
}

// ======================= K2: HMMA GEMM + partial LSE (R8-best version) =======================
// 256 threads, 8 warps in 4x2 grid, warp tile 32x64. 3-stage cp.async pipeline,
// fully-unrolled kc loop, decomposed swizzle, same-chunk fragment prefetch.
__global__ void __launch_bounds__(256, 2) k_gemm() {
    extern __shared__ char dsm[];
    uint32_t base = smem_u32(dsm);
    uint32_t A = (base + 1023u) & ~1023u;
    char* SA = dsm + (A - base);

    int tid = threadIdx.x;
    int wid = tid >> 5;
    int lid = tid & 31;
    int warpM = wid >> 1;          // 0..3  (32 batch rows each)
    int warpN = wid & 1;           // 0..1  (64 class cols each)

    int ctile = blockIdx.x >> 2;
    int btile = blockIdx.x & 3;
    int cls0 = ctile * 128;
    int b0 = btile * 128;

    // swz(r*128 + c) = r*128 + (c ^ ((r&7)<<4))  for c < 128
    int lrow = tid >> 3;                   // 0..31
    int lcol = (tid & 7) * 16;
    uint32_t st_sw = A + (uint32_t)(lrow * 128 + (lcol ^ ((lrow & 7) << 4)));
    const char* pA = (const char*)g_xn + (size_t)b0 * 1024 + lrow * 1024 + (tid & 7) * 16;
    const char* pB = (const char*)g_wb + (size_t)cls0 * 1024 + lrow * 1024 + (tid & 7) * 16;

    auto ld = [&](int kc, int st) {
        #pragma unroll
        for (int i = 0; i < 4; i++)
            cp_async16_ca(st_sw + st * SM_STAGE + i * 4096, pA + i * 32768 + kc * 128);
        #pragma unroll
        for (int i = 0; i < 4; i++)
            cp_async16_cg(st_sw + st * SM_STAGE + 16384 + i * 4096, pB + i * 32768 + kc * 128);
        cp_commit();
    };

    int lr = lid & 15;
    int lh = (lid >> 4) * 16;
    uint32_t pat = (uint32_t)((lr & 7) << 4);
    uint32_t ko[4];
    #pragma unroll
    for (int ks = 0; ks < 4; ks++) ko[ks] = (uint32_t)((ks * 32 + lh) ^ pat);
    uint32_t ldA = A + (uint32_t)((warpM * 32 + lr) * 128);
    uint32_t ldB = A + 16384u + (uint32_t)((warpN * 64 + lr) * 128);

    float acc[2][8][4];
    #pragma unroll
    for (int i = 0; i < 2; i++)
        #pragma unroll
        for (int j = 0; j < 8; j++)
            #pragma unroll
            for (int q = 0; q < 4; q++) acc[i][j][q] = 0.0f;

    int* tgt_s = (int*)(SA + SM_TGT);
    if (tid < 128) tgt_s[tid] = g_tgt[b0 + tid];

    ld(0, 0);
    ld(1, 1);

    uint32_t bfr[2][4][4];
    uint32_t afr[2][2][4];

    #pragma unroll
    for (int kc = 0; kc < NCHUNK; kc++) {
        if (kc < NCHUNK - 1) cp_wait<1>();
        else                 cp_wait<0>();
        __syncthreads();

        if (kc + 2 < NCHUNK) ld(kc + 2, (kc + 2) % 3);

        const uint32_t sOff = (uint32_t)((kc % 3) * SM_STAGE);

        #pragma unroll
        for (int nt4 = 0; nt4 < 4; nt4++)
            ldsm_x4(bfr[0][nt4], ldB + sOff + nt4 * 2048 + ko[0]);
        #pragma unroll
        for (int mt = 0; mt < 2; mt++)
            ldsm_x4(afr[0][mt], ldA + sOff + mt * 2048 + ko[0]);

        #pragma unroll
        for (int ks = 0; ks < 4; ks++) {
            int cur = ks & 1;
            int nxt = cur ^ 1;
            if (ks < 3) {
                #pragma unroll
                for (int nt4 = 0; nt4 < 4; nt4++)
                    ldsm_x4(bfr[nxt][nt4], ldB + sOff + nt4 * 2048 + ko[ks + 1]);
                #pragma unroll
                for (int mt = 0; mt < 2; mt++)
                    ldsm_x4(afr[nxt][mt], ldA + sOff + mt * 2048 + ko[ks + 1]);
            }
            #pragma unroll
            for (int mt = 0; mt < 2; mt++) {
                #pragma unroll
                for (int nt4 = 0; nt4 < 4; nt4++) {
                    mma_bf16(acc[mt][nt4 * 2 + 0], afr[cur][mt], bfr[cur][nt4][0], bfr[cur][nt4][2]);
                    mma_bf16(acc[mt][nt4 * 2 + 1], afr[cur][mt], bfr[cur][nt4][1], bfr[cur][nt4][3]);
                }
            }
        }
        __syncthreads();
    }

    // ---------------- epilogue: deterministic partial LSE ----------------
    float* rsum = (float*)(SA + SM_RSUM);
    int g = lid >> 2;
    int tg = lid & 3;

    float rs[4] = {0.f, 0.f, 0.f, 0.f};
    #pragma unroll
    for (int mt = 0; mt < 2; mt++) {
        int rlo = warpM * 32 + mt * 16 + g;
        int rhi = rlo + 8;
        int tlo = tgt_s[rlo];
        int thi = tgt_s[rhi];
        #pragma unroll
        for (int nt = 0; nt < 8; nt++) {
            int colb = warpN * 64 + nt * 8 + tg * 2;
            #pragma unroll
            for (int q = 0; q < 4; q++) {
                int cls = cls0 + colb + (q & 1);
                float cosv = acc[mt][nt][q];
                int row = (q < 2) ? rlo : rhi;
                int t = (q < 2) ? tlo : thi;
                if (cls == t) {
                    g_cost[b0 + row] = cosv;
                } else if (cls < CLASSES) {
                    rs[mt * 2 + (q >> 1)] += exp2f(fmaf(EXPK, cosv, -EXPK));
                }
            }
        }
    }
    #pragma unroll
    for (int i = 0; i < 4; i++) {
        rs[i] += __shfl_xor_sync(0xffffffffu, rs[i], 1);
        rs[i] += __shfl_xor_sync(0xffffffffu, rs[i], 2);
    }
    if (tg == 0) {
        #pragma unroll
        for (int mt = 0; mt < 2; mt++) {
            int rlo = warpM * 32 + mt * 16 + g;
            rsum[rlo * 2 + warpN] = rs[mt * 2 + 0];
            rsum[(rlo + 8) * 2 + warpN] = rs[mt * 2 + 1];
        }
    }
    __syncthreads();
    if (tid < 128) {
        g_partials[(size_t)(b0 + tid) * PPAD + ctile] = rsum[tid * 2] + rsum[tid * 2 + 1];
    }
}

// ======================= K3: per-batch reduce + margin (warp per batch row) ==========
__global__ void __launch_bounds__(256) k_reduce_b() {
    int wid = threadIdx.x >> 5;
    int lane = threadIdx.x & 31;
    int b = blockIdx.x * 8 + wid;          // 64 blocks * 8 warps = 512 rows
    float acc = 0.0f;
    for (int i = lane; i < NCTA; i += 32)
        acc += g_partials[(size_t)b * PPAD + i];
    #pragma unroll
    for (int m = 16; m >= 1; m >>= 1) acc += __shfl_xor_sync(0xffffffffu, acc, m);
    if (lane == 0) {
        float ct = g_cost[b];
        float st = sqrtf(fmaxf(1.0f - ct * ct, 0.0f));
        float phi = ct * C_COS_M - st * C_SIN_M;
        phi = (ct > C_TH) ? phi : (ct - C_MM);
        acc += exp2f(EXPK * (phi - 1.0f));
        g_lossb[b] = 64.0f + logf(acc) - 64.0f * phi;
    }
}

// ======================= K4: mean over batch =======================
__global__ void __launch_bounds__(512) k_finalize(float* __restrict__ out) {
    __shared__ float red[16];
    int tid = threadIdx.x;
    float v = g_lossb[tid];
    #pragma unroll
    for (int m = 16; m >= 1; m >>= 1) v += __shfl_xor_sync(0xffffffffu, v, m);
    if ((tid & 31) == 0) red[tid >> 5] = v;
    __syncthreads();
    if (tid < 16) {
        float s = red[tid];
        #pragma unroll
        for (int m = 8; m >= 1; m >>= 1) s += __shfl_xor_sync(0xffffu, s, m);
        if (tid == 0) out[0] = s * (1.0f / (float)BATCHN);
    }
}

// ======================= launch =======================
extern "C" void kernel_launch(void* const* d_in, const int* in_sizes, int n_in,
                              void* d_out, int out_size) {
    const float* x = (const float*)d_in[0];
    const float* w = (const float*)d_in[1];
    const int* tgt_raw = (const int*)d_in[2];
    float* out = (float*)d_out;

    cudaFuncSetAttribute(k_gemm, cudaFuncAttributeMaxDynamicSharedMemorySize, SMEM_DYN);

    k_prep_targets<<<1, 512>>>(tgt_raw);
    k_norm_w<<<CPAD / 4, 128>>>(w);
    k_norm_x<<<BATCHN, 128>>>(x);
    k_gemm<<<NCTA * 4, 256, SMEM_DYN>>>();
    k_reduce_b<<<64, 256>>>();
    k_finalize<<<1, 512>>>(out);
}